// round 5
// baseline (speedup 1.0000x reference)
#include <cuda_runtime.h>
#include <cuda_bf16.h>
#include <stdint.h>

// NeRF fused MLP via mma.sync (HMMA) bf16 hi/lo split-3, m=2 per warp.
// CTA = 128 threads (4 warps); each warp computes a 32-point row tile through
// all 7 layers. Weights in SMEM in B-fragment order:
//   [ktile][nt][lane] -> {bh0, bh1, bl0, bl1}; one ld.shared.v4 feeds 6 MMAs.

#define XDIM 48

// frag-order smem byte offsets: layer size = KT*NT*32*16
#define S0F 0        // KT2 NT8:  8192
#define S1F 8192     // KT4 NT8: 16384
#define S2F 24576    // KT4 NT2:  4096
#define C0F 28672    // KT2 NT8:  8192
#define C1F 36864    // KT4 NT8: 16384
#define C2F 53248    // KT4 NT8: 16384
#define C3F 69632    // KT4 NT1:  4096
#define OUTS 73728   // 128 rows * 16B = 2048
#define SMEM_TOTAL 75776

__device__ __forceinline__ uint32_t smem_u32(const void* p) {
    uint32_t a;
    asm("{ .reg .u64 t; cvta.to.shared.u64 t, %1; cvt.u32.u64 %0, t; }"
        : "=r"(a) : "l"(p));
    return a;
}
__device__ __forceinline__ uint4 lds128(uint32_t a) {
    uint4 v;
    asm volatile("ld.shared.v4.b32 {%0,%1,%2,%3}, [%4];"
                 : "=r"(v.x), "=r"(v.y), "=r"(v.z), "=r"(v.w) : "r"(a));
    return v;
}
__device__ __forceinline__ void sts_f(uint32_t a, float v) {
    asm volatile("st.shared.f32 [%0], %1;" :: "r"(a), "f"(v) : "memory");
}
__device__ __forceinline__ float4 lds_f4v(uint32_t a) {
    float4 v;
    asm volatile("ld.shared.v4.f32 {%0,%1,%2,%3}, [%4];"
                 : "=f"(v.x), "=f"(v.y), "=f"(v.z), "=f"(v.w) : "r"(a));
    return v;
}

__device__ __forceinline__ void mma_bf16(float* d, const uint32_t* a,
                                         uint32_t b0, uint32_t b1) {
    asm("mma.sync.aligned.m16n8k16.row.col.f32.bf16.bf16.f32 "
        "{%0,%1,%2,%3},{%4,%5,%6,%7},{%8,%9},{%0,%1,%2,%3};"
        : "+f"(d[0]), "+f"(d[1]), "+f"(d[2]), "+f"(d[3])
        : "r"(a[0]), "r"(a[1]), "r"(a[2]), "r"(a[3]), "r"(b0), "r"(b1));
}

// exact truncation split: hi = bits(a)&0xFFFF0000 (exact bf16), lo = bf16(a-hi)
#define SPLIT2(a0, a1, H, L) do { \
    float _s0 = (a0), _s1 = (a1); \
    uint32_t _u0 = __float_as_uint(_s0) & 0xFFFF0000u; \
    uint32_t _u1 = __float_as_uint(_s1) & 0xFFFF0000u; \
    (H) = (_u0 >> 16) | _u1; \
    __nv_bfloat162 _lb = __floats2bfloat162_rn(_s0 - __uint_as_float(_u0), \
                                               _s1 - __uint_as_float(_u1)); \
    (L) = *reinterpret_cast<uint32_t*>(&_lb); \
} while (0)

#define RELU_SPLIT2(a0, a1, H, L) SPLIT2(fmaxf((a0), 0.0f), fmaxf((a1), 0.0f), H, L)

// stage a plain [K][N] row-major weight matrix into fragment order
__device__ __forceinline__ void stage_plain(const float* __restrict__ W, int N,
                                            int KT, int NT, char* dst, int tid) {
    const int total = KT * NT * 32;
    for (int idx = tid; idx < total; idx += 128) {
        int lane = idx & 31;
        int grp = idx >> 5;
        int nt = grp % NT, kt = grp / NT;
        int q = lane & 3, nr = lane >> 2;
        int nn = nt * 8 + nr;
        int k0 = kt * 16 + 2 * q;
        float w00 = W[k0 * N + nn],       w01 = W[(k0 + 1) * N + nn];
        float w10 = W[(k0 + 8) * N + nn], w11 = W[(k0 + 9) * N + nn];
        uint4 f;
        SPLIT2(w00, w01, f.x, f.z);
        SPLIT2(w10, w11, f.y, f.w);
        reinterpret_cast<uint4*>(dst)[idx] = f;
    }
}

// inner GEMM: KT k16-tiles x NT n8-tiles x m2, split-3; 1 LDS.128 -> 6 MMAs
#define GEMM_LAYER(KT, NT, OFF) do { \
    _Pragma("unroll") \
    for (int k = 0; k < (KT); k++) { \
        _Pragma("unroll") \
        for (int nt = 0; nt < (NT); nt++) { \
            uint4 _b = lds128(sb + (OFF) + \
                (uint32_t)(((k * (NT) + nt) * 32 + lane) * 16)); \
            _Pragma("unroll") \
            for (int m = 0; m < 2; m++) { \
                mma_bf16(D[m][nt], Ah[m][k], _b.x, _b.y); \
                mma_bf16(D[m][nt], Ah[m][k], _b.z, _b.w); \
                mma_bf16(D[m][nt], Al[m][k], _b.x, _b.y); \
            } \
        } \
    } \
} while (0)

#define ZERO_D(NT) do { \
    _Pragma("unroll") for (int m = 0; m < 2; m++) \
    _Pragma("unroll") for (int nt = 0; nt < (NT); nt++) \
    _Pragma("unroll") for (int i = 0; i < 4; i++) D[m][nt][i] = 0.0f; \
} while (0)

// relu + split D[m][8][4] -> Ah/Al[m][4][4]
#define EPI_RELU() do { \
    _Pragma("unroll") \
    for (int m = 0; m < 2; m++) { \
        _Pragma("unroll") \
        for (int j = 0; j < 4; j++) { \
            RELU_SPLIT2(D[m][2*j][0],   D[m][2*j][1],   Ah[m][j][0], Al[m][j][0]); \
            RELU_SPLIT2(D[m][2*j][2],   D[m][2*j][3],   Ah[m][j][1], Al[m][j][1]); \
            RELU_SPLIT2(D[m][2*j+1][0], D[m][2*j+1][1], Ah[m][j][2], Al[m][j][2]); \
            RELU_SPLIT2(D[m][2*j+1][2], D[m][2*j+1][3], Ah[m][j][3], Al[m][j][3]); \
        } \
    } \
} while (0)

__global__ void __launch_bounds__(128, 2)
nerf_hmma3_kernel(const float* __restrict__ x,
                  const float* __restrict__ s0, const float* __restrict__ s1,
                  const float* __restrict__ s2, const float* __restrict__ c0,
                  const float* __restrict__ c1, const float* __restrict__ c2,
                  const float* __restrict__ c3,
                  float* __restrict__ out, int n) {
    extern __shared__ char sm[];
    const uint32_t sb = smem_u32(sm);

    const int tid = threadIdx.x;
    const int wid = tid >> 5;      // 0..3
    const int lane = tid & 31;
    const int q = lane & 3;
    const int nrow = lane >> 2;

    // ---------- stage split weights in fragment order ----------
    stage_plain(s0, 64, 2, 8, sm + S0F, tid);
    stage_plain(s1, 64, 4, 8, sm + S1F, tid);
    stage_plain(s2, 16, 4, 2, sm + S2F, tid);
    stage_plain(c1, 64, 4, 8, sm + C1F, tid);
    stage_plain(c2, 64, 4, 8, sm + C2F, tid);
    // c0: cat layout [views(16) | zero-row@16 | geo(15)] => K=32
    {
        const int total = 2 * 8 * 32;
        for (int idx = tid; idx < total; idx += 128) {
            int lane2 = idx & 31;
            int grp = idx >> 5;
            int nt = grp % 8, kt = grp / 8;
            int q2 = lane2 & 3, nr = lane2 >> 2;
            int nn = nt * 8 + nr;
            int k0 = kt * 16 + 2 * q2;
            auto w = [&](int k) -> float {
                return (k < 16) ? c0[k * 64 + nn]
                                : ((k == 16) ? 0.0f : c0[(k - 1) * 64 + nn]);
            };
            uint4 f;
            SPLIT2(w(k0),     w(k0 + 1), f.x, f.z);
            SPLIT2(w(k0 + 8), w(k0 + 9), f.y, f.w);
            reinterpret_cast<uint4*>(sm + C0F)[idx] = f;
        }
    }
    // c3: K=64, N pad 3->8
    {
        const int total = 4 * 1 * 32;
        for (int idx = tid; idx < total; idx += 128) {
            int lane2 = idx & 31;
            int kt = idx >> 5;
            int q2 = lane2 & 3, nr = lane2 >> 2;
            int k0 = kt * 16 + 2 * q2;
            float w00 = (nr < 3) ? c3[k0 * 3 + nr] : 0.0f;
            float w01 = (nr < 3) ? c3[(k0 + 1) * 3 + nr] : 0.0f;
            float w10 = (nr < 3) ? c3[(k0 + 8) * 3 + nr] : 0.0f;
            float w11 = (nr < 3) ? c3[(k0 + 9) * 3 + nr] : 0.0f;
            uint4 f;
            SPLIT2(w00, w01, f.x, f.z);
            SPLIT2(w10, w11, f.y, f.w);
            reinterpret_cast<uint4*>(sm + C3F)[idx] = f;
        }
    }
    __syncthreads();

    const int ntiles = (n + 127) >> 7;

    for (int tile = blockIdx.x; tile < ntiles; tile += gridDim.x) {
        const int base = tile * 128 + wid * 32;

        uint32_t Ah[2][4][4], Al[2][4][4];
        uint32_t Vh[2][4], Vl[2][4];
        float D[2][8][4];
        float sigL[2], sigH[2];

        // ---------- load X rows, build A frags (s0) + view frags ----------
#pragma unroll
        for (int m = 0; m < 2; m++) {
            int r0 = base + m * 16 + nrow;
            int r1 = r0 + 8;
            if (r0 >= n) r0 = n - 1;
            if (r1 >= n) r1 = n - 1;
            const float* p0 = x + (size_t)r0 * XDIM;
            const float* p1 = x + (size_t)r1 * XDIM;
#pragma unroll
            for (int t = 0; t < 2; t++) {
                float2 a00 = *(const float2*)(p0 + t * 16 + 2 * q);
                float2 a10 = *(const float2*)(p1 + t * 16 + 2 * q);
                float2 a01 = *(const float2*)(p0 + t * 16 + 2 * q + 8);
                float2 a11 = *(const float2*)(p1 + t * 16 + 2 * q + 8);
                SPLIT2(a00.x, a00.y, Ah[m][t][0], Al[m][t][0]);
                SPLIT2(a10.x, a10.y, Ah[m][t][1], Al[m][t][1]);
                SPLIT2(a01.x, a01.y, Ah[m][t][2], Al[m][t][2]);
                SPLIT2(a11.x, a11.y, Ah[m][t][3], Al[m][t][3]);
            }
            float2 v00 = *(const float2*)(p0 + 32 + 2 * q);
            float2 v10 = *(const float2*)(p1 + 32 + 2 * q);
            float2 v01 = *(const float2*)(p0 + 40 + 2 * q);
            float2 v11 = *(const float2*)(p1 + 40 + 2 * q);
            SPLIT2(v00.x, v00.y, Vh[m][0], Vl[m][0]);
            SPLIT2(v10.x, v10.y, Vh[m][1], Vl[m][1]);
            SPLIT2(v01.x, v01.y, Vh[m][2], Vl[m][2]);
            SPLIT2(v11.x, v11.y, Vh[m][3], Vl[m][3]);
        }

        // ---------- sigma net ----------
        ZERO_D(8);
        GEMM_LAYER(2, 8, S0F);
        EPI_RELU();

        ZERO_D(8);
        GEMM_LAYER(4, 8, S1F);
        EPI_RELU();

        ZERO_D(2);
        GEMM_LAYER(4, 2, S2F);

        // sigma + cat = [views | s2out raw (col0=sigma hits zero weight row)]
#pragma unroll
        for (int m = 0; m < 2; m++) {
            sigL[m] = D[m][0][0];
            sigH[m] = D[m][0][2];
            SPLIT2(D[m][0][0], D[m][0][1], Ah[m][1][0], Al[m][1][0]);
            SPLIT2(D[m][0][2], D[m][0][3], Ah[m][1][1], Al[m][1][1]);
            SPLIT2(D[m][1][0], D[m][1][1], Ah[m][1][2], Al[m][1][2]);
            SPLIT2(D[m][1][2], D[m][1][3], Ah[m][1][3], Al[m][1][3]);
#pragma unroll
            for (int i = 0; i < 4; i++) { Ah[m][0][i] = Vh[m][i]; Al[m][0][i] = Vl[m][i]; }
        }

        // ---------- color net ----------
        ZERO_D(8);
        GEMM_LAYER(2, 8, C0F);
        EPI_RELU();

        ZERO_D(8);
        GEMM_LAYER(4, 8, C1F);
        EPI_RELU();

        ZERO_D(8);
        GEMM_LAYER(4, 8, C2F);
        EPI_RELU();

        ZERO_D(1);
        GEMM_LAYER(4, 1, C3F);

        // ---------- output via SMEM scratch, coalesced float4 ----------
#pragma unroll
        for (int m = 0; m < 2; m++) {
            uint32_t s0a = sb + OUTS + (uint32_t)(wid * 32 + m * 16 + nrow) * 16;
            uint32_t s1a = s0a + 8 * 16;
            if (q == 0) {
                sts_f(s0a + 0,  D[m][0][0]);
                sts_f(s0a + 4,  D[m][0][1]);
                sts_f(s0a + 12, sigL[m]);
                sts_f(s1a + 0,  D[m][0][2]);
                sts_f(s1a + 4,  D[m][0][3]);
                sts_f(s1a + 12, sigH[m]);
            } else if (q == 1) {
                sts_f(s0a + 8, D[m][0][0]);
                sts_f(s1a + 8, D[m][0][2]);
            }
        }
        __syncwarp();
        {
            int orow = base + lane;
            if (orow < n) {
                float4 v = lds_f4v(sb + OUTS + (uint32_t)(wid * 32 + lane) * 16);
                reinterpret_cast<float4*>(out)[orow] = v;
            }
        }
        __syncwarp();
    }
}

extern "C" void kernel_launch(void* const* d_in, const int* in_sizes, int n_in,
                              void* d_out, int out_size) {
    const float* x  = (const float*)d_in[0];
    const float* s0 = (const float*)d_in[1];
    const float* s1 = (const float*)d_in[2];
    const float* s2 = (const float*)d_in[3];
    const float* c0 = (const float*)d_in[4];
    const float* c1 = (const float*)d_in[5];
    const float* c2 = (const float*)d_in[6];
    const float* c3 = (const float*)d_in[7];
    float* out = (float*)d_out;

    const int n = in_sizes[0] / XDIM;

    cudaFuncSetAttribute(nerf_hmma3_kernel,
                         cudaFuncAttributeMaxDynamicSharedMemorySize, SMEM_TOTAL);

    // 2 CTAs/SM x 152 SMs (guaranteed by __launch_bounds__(128,2))
    nerf_hmma3_kernel<<<304, 128, SMEM_TOTAL>>>(x, s0, s1, s2, c0, c1, c2, c3,
                                                out, n);
}

// round 6
// speedup vs baseline: 1.0488x; 1.0488x over previous
#include <cuda_runtime.h>
#include <cuda_bf16.h>
#include <stdint.h>

// NeRF fused MLP via mma.sync (HMMA) bf16 hi/lo split-3, m=1 per warp.
// CTA = 256 threads (8 warps); each warp computes a 16-point row tile.
// Inner GEMM hoists all B fragments of a k-group into registers, then issues
// MMAs term-major so same-accumulator MMAs are NT issues apart (no RAW bubbles).

#define XDIM 48

// frag-order smem byte offsets: layer size = KT*NT*32*16
#define S0F 0        // KT2 NT8:  8192
#define S1F 8192     // KT4 NT8: 16384
#define S2F 24576    // KT4 NT2:  4096
#define C0F 28672    // KT2 NT8:  8192
#define C1F 36864    // KT4 NT8: 16384
#define C2F 53248    // KT4 NT8: 16384
#define C3F 69632    // KT4 NT1:  4096
#define OUTS 73728   // 8 warps * 16 rows * 16B = 2048
#define SMEM_TOTAL 75776

__device__ __forceinline__ uint32_t smem_u32(const void* p) {
    uint32_t a;
    asm("{ .reg .u64 t; cvta.to.shared.u64 t, %1; cvt.u32.u64 %0, t; }"
        : "=r"(a) : "l"(p));
    return a;
}
__device__ __forceinline__ uint4 lds128(uint32_t a) {
    uint4 v;
    asm volatile("ld.shared.v4.b32 {%0,%1,%2,%3}, [%4];"
                 : "=r"(v.x), "=r"(v.y), "=r"(v.z), "=r"(v.w) : "r"(a));
    return v;
}
__device__ __forceinline__ void sts_f(uint32_t a, float v) {
    asm volatile("st.shared.f32 [%0], %1;" :: "r"(a), "f"(v) : "memory");
}
__device__ __forceinline__ float4 lds_f4v(uint32_t a) {
    float4 v;
    asm volatile("ld.shared.v4.f32 {%0,%1,%2,%3}, [%4];"
                 : "=f"(v.x), "=f"(v.y), "=f"(v.z), "=f"(v.w) : "r"(a));
    return v;
}

__device__ __forceinline__ void mma_bf16(float* d, const uint32_t* a,
                                         uint32_t b0, uint32_t b1) {
    asm("mma.sync.aligned.m16n8k16.row.col.f32.bf16.bf16.f32 "
        "{%0,%1,%2,%3},{%4,%5,%6,%7},{%8,%9},{%0,%1,%2,%3};"
        : "+f"(d[0]), "+f"(d[1]), "+f"(d[2]), "+f"(d[3])
        : "r"(a[0]), "r"(a[1]), "r"(a[2]), "r"(a[3]), "r"(b0), "r"(b1));
}

// exact truncation split: hi = bits(a)&0xFFFF0000 (exact bf16), lo = bf16(a-hi)
// hi-pack via PRMT: {a0[31:16], a1[31:16]}
#define SPLIT2(a0, a1, H, L) do { \
    float _s0 = (a0), _s1 = (a1); \
    uint32_t _b0 = __float_as_uint(_s0); \
    uint32_t _b1 = __float_as_uint(_s1); \
    (H) = __byte_perm(_b0, _b1, 0x7632); \
    float _r0 = _s0 - __uint_as_float(_b0 & 0xFFFF0000u); \
    float _r1 = _s1 - __uint_as_float(_b1 & 0xFFFF0000u); \
    __nv_bfloat162 _lb = __floats2bfloat162_rn(_r0, _r1); \
    (L) = *reinterpret_cast<uint32_t*>(&_lb); \
} while (0)

#define RELU_SPLIT2(a0, a1, H, L) SPLIT2(fmaxf((a0), 0.0f), fmaxf((a1), 0.0f), H, L)

// stage a plain [K][N] row-major weight matrix into fragment order
__device__ __forceinline__ void stage_plain(const float* __restrict__ W, int N,
                                            int KT, int NT, char* dst, int tid) {
    const int total = KT * NT * 32;
    for (int idx = tid; idx < total; idx += 256) {
        int lane = idx & 31;
        int grp = idx >> 5;
        int nt = grp % NT, kt = grp / NT;
        int q = lane & 3, nr = lane >> 2;
        int nn = nt * 8 + nr;
        int k0 = kt * 16 + 2 * q;
        float w00 = W[k0 * N + nn],       w01 = W[(k0 + 1) * N + nn];
        float w10 = W[(k0 + 8) * N + nn], w11 = W[(k0 + 9) * N + nn];
        uint4 f;
        SPLIT2(w00, w01, f.x, f.z);
        SPLIT2(w10, w11, f.y, f.w);
        reinterpret_cast<uint4*>(dst)[idx] = f;
    }
}

// inner GEMM: per k-group, hoist NT B fragments, then term-major MMA issue.
#define GEMM_LAYER(KT, NT, OFF) do { \
    _Pragma("unroll") \
    for (int k = 0; k < (KT); k++) { \
        uint4 B[(NT)]; \
        _Pragma("unroll") \
        for (int nt = 0; nt < (NT); nt++) \
            B[nt] = lds128(sb + (OFF) + \
                (uint32_t)(((k * (NT) + nt) * 32 + lane) * 16)); \
        _Pragma("unroll") \
        for (int nt = 0; nt < (NT); nt++) \
            mma_bf16(D[nt], Ah[k], B[nt].x, B[nt].y); \
        _Pragma("unroll") \
        for (int nt = 0; nt < (NT); nt++) \
            mma_bf16(D[nt], Ah[k], B[nt].z, B[nt].w); \
        _Pragma("unroll") \
        for (int nt = 0; nt < (NT); nt++) \
            mma_bf16(D[nt], Al[k], B[nt].x, B[nt].y); \
    } \
} while (0)

#define ZERO_D(NT) do { \
    _Pragma("unroll") for (int nt = 0; nt < (NT); nt++) \
    _Pragma("unroll") for (int i = 0; i < 4; i++) D[nt][i] = 0.0f; \
} while (0)

// relu + split D[8][4] -> Ah/Al[4][4]
#define EPI_RELU() do { \
    _Pragma("unroll") \
    for (int j = 0; j < 4; j++) { \
        RELU_SPLIT2(D[2*j][0],   D[2*j][1],   Ah[j][0], Al[j][0]); \
        RELU_SPLIT2(D[2*j][2],   D[2*j][3],   Ah[j][1], Al[j][1]); \
        RELU_SPLIT2(D[2*j+1][0], D[2*j+1][1], Ah[j][2], Al[j][2]); \
        RELU_SPLIT2(D[2*j+1][2], D[2*j+1][3], Ah[j][3], Al[j][3]); \
    } \
} while (0)

__global__ void __launch_bounds__(256, 2)
nerf_hmma4_kernel(const float* __restrict__ x,
                  const float* __restrict__ s0, const float* __restrict__ s1,
                  const float* __restrict__ s2, const float* __restrict__ c0,
                  const float* __restrict__ c1, const float* __restrict__ c2,
                  const float* __restrict__ c3,
                  float* __restrict__ out, int n) {
    extern __shared__ char sm[];
    const uint32_t sb = smem_u32(sm);

    const int tid = threadIdx.x;
    const int wid = tid >> 5;      // 0..7
    const int lane = tid & 31;
    const int q = lane & 3;
    const int nrow = lane >> 2;

    // ---------- stage split weights in fragment order ----------
    stage_plain(s0, 64, 2, 8, sm + S0F, tid);
    stage_plain(s1, 64, 4, 8, sm + S1F, tid);
    stage_plain(s2, 16, 4, 2, sm + S2F, tid);
    stage_plain(c1, 64, 4, 8, sm + C1F, tid);
    stage_plain(c2, 64, 4, 8, sm + C2F, tid);
    // c0: cat layout [views(16) | zero-row@16 | geo(15)] => K=32
    {
        const int total = 2 * 8 * 32;
        for (int idx = tid; idx < total; idx += 256) {
            int lane2 = idx & 31;
            int grp = idx >> 5;
            int nt = grp % 8, kt = grp / 8;
            int q2 = lane2 & 3, nr = lane2 >> 2;
            int nn = nt * 8 + nr;
            int k0 = kt * 16 + 2 * q2;
            auto w = [&](int k) -> float {
                return (k < 16) ? c0[k * 64 + nn]
                                : ((k == 16) ? 0.0f : c0[(k - 1) * 64 + nn]);
            };
            uint4 f;
            SPLIT2(w(k0),     w(k0 + 1), f.x, f.z);
            SPLIT2(w(k0 + 8), w(k0 + 9), f.y, f.w);
            reinterpret_cast<uint4*>(sm + C0F)[idx] = f;
        }
    }
    // c3: K=64, N pad 3->8
    {
        const int total = 4 * 1 * 32;
        for (int idx = tid; idx < total; idx += 256) {
            int lane2 = idx & 31;
            int kt = idx >> 5;
            int q2 = lane2 & 3, nr = lane2 >> 2;
            int k0 = kt * 16 + 2 * q2;
            float w00 = (nr < 3) ? c3[k0 * 3 + nr] : 0.0f;
            float w01 = (nr < 3) ? c3[(k0 + 1) * 3 + nr] : 0.0f;
            float w10 = (nr < 3) ? c3[(k0 + 8) * 3 + nr] : 0.0f;
            float w11 = (nr < 3) ? c3[(k0 + 9) * 3 + nr] : 0.0f;
            uint4 f;
            SPLIT2(w00, w01, f.x, f.z);
            SPLIT2(w10, w11, f.y, f.w);
            reinterpret_cast<uint4*>(sm + C3F)[idx] = f;
        }
    }
    __syncthreads();

    const int ntiles = (n + 127) >> 7;

    for (int tile = blockIdx.x; tile < ntiles; tile += gridDim.x) {
        const int base = tile * 128 + wid * 16;

        uint32_t Ah[4][4], Al[4][4];
        uint32_t Vh[4], Vl[4];
        float D[8][4];
        float sigL, sigH;

        // ---------- load X rows, build A frags (s0) + view frags ----------
        {
            int r0 = base + nrow;
            int r1 = r0 + 8;
            if (r0 >= n) r0 = n - 1;
            if (r1 >= n) r1 = n - 1;
            const float* p0 = x + (size_t)r0 * XDIM;
            const float* p1 = x + (size_t)r1 * XDIM;
#pragma unroll
            for (int t = 0; t < 2; t++) {
                float2 a00 = *(const float2*)(p0 + t * 16 + 2 * q);
                float2 a10 = *(const float2*)(p1 + t * 16 + 2 * q);
                float2 a01 = *(const float2*)(p0 + t * 16 + 2 * q + 8);
                float2 a11 = *(const float2*)(p1 + t * 16 + 2 * q + 8);
                SPLIT2(a00.x, a00.y, Ah[t][0], Al[t][0]);
                SPLIT2(a10.x, a10.y, Ah[t][1], Al[t][1]);
                SPLIT2(a01.x, a01.y, Ah[t][2], Al[t][2]);
                SPLIT2(a11.x, a11.y, Ah[t][3], Al[t][3]);
            }
            float2 v00 = *(const float2*)(p0 + 32 + 2 * q);
            float2 v10 = *(const float2*)(p1 + 32 + 2 * q);
            float2 v01 = *(const float2*)(p0 + 40 + 2 * q);
            float2 v11 = *(const float2*)(p1 + 40 + 2 * q);
            SPLIT2(v00.x, v00.y, Vh[0], Vl[0]);
            SPLIT2(v10.x, v10.y, Vh[1], Vl[1]);
            SPLIT2(v01.x, v01.y, Vh[2], Vl[2]);
            SPLIT2(v11.x, v11.y, Vh[3], Vl[3]);
        }

        // ---------- sigma net ----------
        ZERO_D(8);
        GEMM_LAYER(2, 8, S0F);
        EPI_RELU();

        ZERO_D(8);
        GEMM_LAYER(4, 8, S1F);
        EPI_RELU();

        ZERO_D(2);
        GEMM_LAYER(4, 2, S2F);

        // sigma + cat = [views | s2out raw (col0=sigma hits zero weight row)]
        sigL = D[0][0];
        sigH = D[0][2];
        SPLIT2(D[0][0], D[0][1], Ah[1][0], Al[1][0]);
        SPLIT2(D[0][2], D[0][3], Ah[1][1], Al[1][1]);
        SPLIT2(D[1][0], D[1][1], Ah[1][2], Al[1][2]);
        SPLIT2(D[1][2], D[1][3], Ah[1][3], Al[1][3]);
#pragma unroll
        for (int i = 0; i < 4; i++) { Ah[0][i] = Vh[i]; Al[0][i] = Vl[i]; }

        // ---------- color net ----------
        ZERO_D(8);
        GEMM_LAYER(2, 8, C0F);
        EPI_RELU();

        ZERO_D(8);
        GEMM_LAYER(4, 8, C1F);
        EPI_RELU();

        ZERO_D(8);
        GEMM_LAYER(4, 8, C2F);
        EPI_RELU();

        ZERO_D(1);
        GEMM_LAYER(4, 1, C3F);

        // ---------- output via warp-local SMEM scratch, coalesced f4 ----------
        {
            uint32_t s0a = sb + OUTS + (uint32_t)(wid * 16 + nrow) * 16;
            uint32_t s1a = s0a + 8 * 16;
            if (q == 0) {
                sts_f(s0a + 0,  D[0][0]);
                sts_f(s0a + 4,  D[0][1]);
                sts_f(s0a + 12, sigL);
                sts_f(s1a + 0,  D[0][2]);
                sts_f(s1a + 4,  D[0][3]);
                sts_f(s1a + 12, sigH);
            } else if (q == 1) {
                sts_f(s0a + 8, D[0][0]);
                sts_f(s1a + 8, D[0][2]);
            }
        }
        __syncwarp();
        if (lane < 16) {
            int orow = base + lane;
            if (orow < n) {
                float4 v = lds_f4v(sb + OUTS + (uint32_t)(wid * 16 + lane) * 16);
                reinterpret_cast<float4*>(out)[orow] = v;
            }
        }
        __syncwarp();
    }
}

extern "C" void kernel_launch(void* const* d_in, const int* in_sizes, int n_in,
                              void* d_out, int out_size) {
    const float* x  = (const float*)d_in[0];
    const float* s0 = (const float*)d_in[1];
    const float* s1 = (const float*)d_in[2];
    const float* s2 = (const float*)d_in[3];
    const float* c0 = (const float*)d_in[4];
    const float* c1 = (const float*)d_in[5];
    const float* c2 = (const float*)d_in[6];
    const float* c3 = (const float*)d_in[7];
    float* out = (float*)d_out;

    const int n = in_sizes[0] / XDIM;

    cudaFuncSetAttribute(nerf_hmma4_kernel,
                         cudaFuncAttributeMaxDynamicSharedMemorySize, SMEM_TOTAL);

    int occ = 0;
    cudaOccupancyMaxActiveBlocksPerMultiprocessor(&occ, nerf_hmma4_kernel, 256,
                                                  SMEM_TOTAL);
    if (occ < 1) occ = 1;
    int blocks = 152 * occ;

    nerf_hmma4_kernel<<<blocks, 256, SMEM_TOTAL>>>(x, s0, s1, s2, c0, c1, c2, c3,
                                                   out, n);
}